// round 3
// baseline (speedup 1.0000x reference)
#include <cuda_runtime.h>
#include <cuda_fp16.h>
#include <cstdint>

// ---------------------------------------------------------------------------
// out[M,N] = x[M,K] @ (codes[N,K] * scale)^T + bias
// M=8192 (B*S), N=4096, K=4096.  Baseline sm_100 ISA: classic HMMA path
// (mma.sync.m16n8k16 + ldmatrix + cp.async multistage).
// ---------------------------------------------------------------------------
#define M_DIM 8192
#define N_DIM 4096
#define K_DIM 4096

#define BM 128
#define BN 128
#define BK 64
#define STAGES 4
#define KITERS (K_DIM / BK)          // 64

#define A_TILE_BYTES (BM * BK * 2)   // 16 KB
#define B_TILE_BYTES (BN * BK * 2)   // 16 KB
#define STAGE_BYTES  (A_TILE_BYTES + B_TILE_BYTES)
#define SMEM_BYTES   (STAGES * STAGE_BYTES)   // 128 KB

// Scratch fp16 copies (device globals: allocation-free per harness rules)
__device__ __align__(1024) __half g_Xh[(size_t)M_DIM * K_DIM];   // 64 MB
__device__ __align__(1024) __half g_Wh[(size_t)N_DIM * K_DIM];   // 32 MB

// ---------------------------------------------------------------------------
// PTX helpers
// ---------------------------------------------------------------------------
__device__ __forceinline__ uint32_t smem_u32(const void* p) {
    uint32_t a;
    asm("{ .reg .u64 t; cvta.to.shared.u64 t, %1; cvt.u32.u64 %0, t; }"
        : "=r"(a) : "l"(p));
    return a;
}

__device__ __forceinline__ void cp16(uint32_t dst, const void* src) {
    asm volatile("cp.async.cg.shared.global [%0], [%1], 16;"
                 :: "r"(dst), "l"(src) : "memory");
}
__device__ __forceinline__ void cp_commit() {
    asm volatile("cp.async.commit_group;" ::: "memory");
}
template <int N>
__device__ __forceinline__ void cp_wait() {
    asm volatile("cp.async.wait_group %0;" :: "n"(N) : "memory");
}

__device__ __forceinline__ void ldmatrix_x4(uint32_t* r, uint32_t addr) {
    asm volatile("ldmatrix.sync.aligned.m8n8.x4.shared.b16 {%0,%1,%2,%3}, [%4];"
                 : "=r"(r[0]), "=r"(r[1]), "=r"(r[2]), "=r"(r[3]) : "r"(addr));
}

__device__ __forceinline__ void mma16816(float* c, const uint32_t* a,
                                         const uint32_t* b) {
    asm volatile(
        "mma.sync.aligned.m16n8k16.row.col.f32.f16.f16.f32 "
        "{%0,%1,%2,%3}, {%4,%5,%6,%7}, {%8,%9}, {%0,%1,%2,%3};"
        : "+f"(c[0]), "+f"(c[1]), "+f"(c[2]), "+f"(c[3])
        : "r"(a[0]), "r"(a[1]), "r"(a[2]), "r"(a[3]), "r"(b[0]), "r"(b[1]));
}

// ---------------------------------------------------------------------------
// Conversion pre-passes: fp32 x -> fp16, int32 codes -> fp16 (exact)
// ---------------------------------------------------------------------------
struct __align__(16) H8 { __half2 a, b, c, d; };
struct __align__(8)  H4 { __half2 a, b; };

__global__ void fp4lin_cvt_x(const float4* __restrict__ x, H8* __restrict__ o, int n8) {
    int i = blockIdx.x * blockDim.x + threadIdx.x;
    if (i >= n8) return;
    float4 v0 = x[2 * i], v1 = x[2 * i + 1];
    H8 h;
    h.a = __floats2half2_rn(v0.x, v0.y);
    h.b = __floats2half2_rn(v0.z, v0.w);
    h.c = __floats2half2_rn(v1.x, v1.y);
    h.d = __floats2half2_rn(v1.z, v1.w);
    o[i] = h;
}

__global__ void fp4lin_cvt_w(const int4* __restrict__ w, H4* __restrict__ o, int n4) {
    int i = blockIdx.x * blockDim.x + threadIdx.x;
    if (i >= n4) return;
    int4 v = w[i];
    H4 h;
    h.a = __halves2half2(__int2half_rn(v.x), __int2half_rn(v.y));
    h.b = __halves2half2(__int2half_rn(v.z), __int2half_rn(v.w));
    o[i] = h;
}

// ---------------------------------------------------------------------------
// GEMM: 128x128x64 CTA tile, 8 warps (2m x 4n, 64x32 warp tile),
// 4-stage cp.async pipeline, XOR-swizzled SMEM, HMMA m16n8k16.
//
// SMEM tile layout (both A and B): [128 rows][8 granules of 16B], granule
// stored at (g ^ (row & 7)) -> conflict-free cp.async stores AND ldmatrix.
// ---------------------------------------------------------------------------
__global__ void __launch_bounds__(256, 1)
fp4lin_gemm(const __half* __restrict__ Ag, const __half* __restrict__ Bg,
            const float* __restrict__ scale_p, const float* __restrict__ bias,
            float* __restrict__ out) {
    extern __shared__ __align__(1024) uint8_t smem[];
    const uint32_t sbase = smem_u32(smem);
    const int tid  = threadIdx.x;
    const int wid  = tid >> 5;
    const int lane = tid & 31;
    const int wm   = wid >> 2;          // 0..1  (m warp)
    const int wn   = wid & 3;           // 0..3  (n warp)
    const int m0   = blockIdx.y * BM;
    const int n0   = blockIdx.x * BN;

    // --- cp.async per-thread mapping (fixed across stages) ---
    // 1024 granules per tile, 256 threads -> 4 granules each, row = trow+i*32.
    const int trow = tid >> 3;                 // 0..31
    const int tgc  = tid & 7;                  // granule col 0..7
    const uint32_t swg   = (uint32_t)(tgc ^ (trow & 7));
    const uint32_t s_off = (uint32_t)trow * 128u + swg * 16u;
    const __half* gA0 = Ag + (size_t)(m0 + trow) * K_DIM + tgc * 8;
    const __half* gB0 = Bg + (size_t)(n0 + trow) * K_DIM + tgc * 8;

    // --- ldmatrix per-lane components ---
    const int rowin   = (lane & 7) | (((lane >> 3) & 1) << 3);  // 0..15
    const int colsel  = lane >> 4;                              // 0..1
    const int lane7   = lane & 7;
    // byte offset of the lane's row within tile, per m-tile / n-tile
    uint32_t aRowOff[4], bRowOff[4];
#pragma unroll
    for (int t = 0; t < 4; t++) {
        aRowOff[t] = (uint32_t)(wm * 64 + t * 16 + rowin) * 128u;
        bRowOff[t] = (uint32_t)(wn * 32 + ((t >> 1) ? 16 : 0) + rowin) * 128u; // only t=0,1 used
    }
    const uint32_t bRow0 = (uint32_t)(wn * 32 + rowin) * 128u;
    const uint32_t bRow1 = (uint32_t)(wn * 32 + 16 + rowin) * 128u;

    float acc[4][4][4];
#pragma unroll
    for (int mt = 0; mt < 4; mt++)
#pragma unroll
        for (int nt = 0; nt < 4; nt++)
#pragma unroll
            for (int e = 0; e < 4; e++) acc[mt][nt][e] = 0.f;

#define LOAD_STAGE(s, kblk)                                                     \
    do {                                                                        \
        const uint32_t sA = sbase + (uint32_t)(s) * STAGE_BYTES;                \
        const uint32_t sB = sA + A_TILE_BYTES;                                  \
        _Pragma("unroll")                                                       \
        for (int i = 0; i < 4; i++) {                                           \
            cp16(sA + s_off + (uint32_t)i * 32u * 128u,                         \
                 gA0 + (size_t)i * 32 * K_DIM + (kblk));                        \
            cp16(sB + s_off + (uint32_t)i * 32u * 128u,                         \
                 gB0 + (size_t)i * 32 * K_DIM + (kblk));                        \
        }                                                                       \
        cp_commit();                                                            \
    } while (0)

    // Prologue: fill STAGES-1 stages
#pragma unroll
    for (int s = 0; s < STAGES - 1; s++) LOAD_STAGE(s, s * BK);

    int sr = 0, sw = STAGES - 1;
    for (int k = 0; k < KITERS; k++) {
        cp_wait<STAGES - 2>();
        __syncthreads();

        // issue the next stage's loads (keeps pipeline full)
        if (k + STAGES - 1 < KITERS) LOAD_STAGE(sw, (k + STAGES - 1) * BK);
        else cp_commit();   // keep wait_group counting consistent

        const uint32_t sA = sbase + (uint32_t)sr * STAGE_BYTES;
        const uint32_t sB = sA + A_TILE_BYTES;

#pragma unroll
        for (int ks = 0; ks < BK / 16; ks++) {
            const uint32_t swz = (uint32_t)(((ks * 2 + colsel) ^ lane7)) * 16u;
            uint32_t a[4][4];
#pragma unroll
            for (int mt = 0; mt < 4; mt++)
                ldmatrix_x4(a[mt], sA + aRowOff[mt] + swz);
            uint32_t b[4][2];
            {
                uint32_t r[4];
                ldmatrix_x4(r, sB + bRow0 + swz);
                b[0][0] = r[0]; b[1][0] = r[1]; b[0][1] = r[2]; b[1][1] = r[3];
                ldmatrix_x4(r, sB + bRow1 + swz);
                b[2][0] = r[0]; b[3][0] = r[1]; b[2][1] = r[2]; b[3][1] = r[3];
            }
#pragma unroll
            for (int mt = 0; mt < 4; mt++)
#pragma unroll
                for (int nt = 0; nt < 4; nt++)
                    mma16816(acc[mt][nt], a[mt], b[nt]);
        }

        sr = (sr + 1) % STAGES;
        sw = (sw + 1) % STAGES;
    }

    // ------------------------------ epilogue -------------------------------
    const float sc = *scale_p;
    const int mbase = m0 + wm * 64 + (lane >> 2);
    const int nbase = n0 + wn * 32 + (lane & 3) * 2;
#pragma unroll
    for (int nt = 0; nt < 4; nt++) {
        const int n = nbase + nt * 8;
        const float2 bb = *reinterpret_cast<const float2*>(bias + n);
#pragma unroll
        for (int mt = 0; mt < 4; mt++) {
            const int m = mbase + mt * 16;
            float2 o0, o1;
            o0.x = acc[mt][nt][0] * sc + bb.x;
            o0.y = acc[mt][nt][1] * sc + bb.y;
            o1.x = acc[mt][nt][2] * sc + bb.x;
            o1.y = acc[mt][nt][3] * sc + bb.y;
            *reinterpret_cast<float2*>(out + (size_t)m * N_DIM + n) = o0;
            *reinterpret_cast<float2*>(out + (size_t)(m + 8) * N_DIM + n) = o1;
        }
    }
#undef LOAD_STAGE
}

// ---------------------------------------------------------------------------
// Host launch
// ---------------------------------------------------------------------------
extern "C" void kernel_launch(void* const* d_in, const int* in_sizes, int n_in,
                              void* d_out, int out_size) {
    (void)in_sizes; (void)n_in; (void)out_size;
    const float* x     = (const float*)d_in[0];
    const int*   w     = (const int*)d_in[1];
    const float* scale = (const float*)d_in[2];
    const float* bias  = (const float*)d_in[3];
    float*       out   = (float*)d_out;

    void *xh = nullptr, *wh = nullptr;
    cudaGetSymbolAddress(&xh, g_Xh);
    cudaGetSymbolAddress(&wh, g_Wh);

    {
        const int n8 = M_DIM * K_DIM / 8;
        fp4lin_cvt_x<<<n8 / 256, 256>>>((const float4*)x, (H8*)xh, n8);
        const int n4 = N_DIM * K_DIM / 4;
        fp4lin_cvt_w<<<n4 / 256, 256>>>((const int4*)w, (H4*)wh, n4);
    }

    static bool attr_set = false;
    if (!attr_set) {
        cudaFuncSetAttribute(fp4lin_gemm,
                             cudaFuncAttributeMaxDynamicSharedMemorySize,
                             SMEM_BYTES);
        attr_set = true;
    }
    dim3 grid(N_DIM / BN, M_DIM / BM);   // x = n (fastest) -> B panels hot in L2
    fp4lin_gemm<<<grid, 256, SMEM_BYTES>>>((const __half*)xh, (const __half*)wh,
                                           scale, bias, out);
}

// round 5
// speedup vs baseline: 1.1014x; 1.1014x over previous
#include <cuda_runtime.h>
#include <cuda_fp16.h>
#include <cstdint>

// ---------------------------------------------------------------------------
// out[M,N] = x[M,K] @ (codes[N,K] * scale)^T + bias
// M=8192, N=4096, K=4096.  Baseline sm_100 ISA: HMMA m16n8k16 + ldmatrix +
// cp.async.  R4 change: 256x128 CTA tile, 512 threads (16 warps -> 4/SMSP)
// to hide LDSM->HMMA latency; 4-stage pipeline, 192 KB SMEM.
// ---------------------------------------------------------------------------
#define M_DIM 8192
#define N_DIM 4096
#define K_DIM 4096

#define BM 256
#define BN 128
#define BK 64
#define STAGES 4
#define KITERS (K_DIM / BK)          // 64

#define A_TILE_BYTES (BM * BK * 2)   // 32 KB
#define B_TILE_BYTES (BN * BK * 2)   // 16 KB
#define STAGE_BYTES  (A_TILE_BYTES + B_TILE_BYTES)   // 48 KB
#define SMEM_BYTES   (STAGES * STAGE_BYTES)          // 192 KB

// Scratch fp16 copies (device globals: allocation-free per harness rules)
__device__ __align__(1024) __half g_Xh[(size_t)M_DIM * K_DIM];   // 64 MB
__device__ __align__(1024) __half g_Wh[(size_t)N_DIM * K_DIM];   // 32 MB

// ---------------------------------------------------------------------------
// PTX helpers
// ---------------------------------------------------------------------------
__device__ __forceinline__ uint32_t smem_u32(const void* p) {
    uint32_t a;
    asm("{ .reg .u64 t; cvta.to.shared.u64 t, %1; cvt.u32.u64 %0, t; }"
        : "=r"(a) : "l"(p));
    return a;
}

__device__ __forceinline__ void cp16(uint32_t dst, const void* src) {
    asm volatile("cp.async.cg.shared.global [%0], [%1], 16;"
                 :: "r"(dst), "l"(src) : "memory");
}
__device__ __forceinline__ void cp_commit() {
    asm volatile("cp.async.commit_group;" ::: "memory");
}
template <int N>
__device__ __forceinline__ void cp_wait() {
    asm volatile("cp.async.wait_group %0;" :: "n"(N) : "memory");
}

__device__ __forceinline__ void ldmatrix_x4(uint32_t* r, uint32_t addr) {
    asm volatile("ldmatrix.sync.aligned.m8n8.x4.shared.b16 {%0,%1,%2,%3}, [%4];"
                 : "=r"(r[0]), "=r"(r[1]), "=r"(r[2]), "=r"(r[3]) : "r"(addr));
}

__device__ __forceinline__ void mma16816(float* c, const uint32_t* a,
                                         const uint32_t* b) {
    asm volatile(
        "mma.sync.aligned.m16n8k16.row.col.f32.f16.f16.f32 "
        "{%0,%1,%2,%3}, {%4,%5,%6,%7}, {%8,%9}, {%0,%1,%2,%3};"
        : "+f"(c[0]), "+f"(c[1]), "+f"(c[2]), "+f"(c[3])
        : "r"(a[0]), "r"(a[1]), "r"(a[2]), "r"(a[3]), "r"(b[0]), "r"(b[1]));
}

// ---------------------------------------------------------------------------
// Conversion pre-passes: fp32 x -> fp16, int32 codes -> fp16 (exact)
// ---------------------------------------------------------------------------
struct __align__(16) H8 { __half2 a, b, c, d; };
struct __align__(8)  H4 { __half2 a, b; };

__global__ void fp4lin_cvt_x(const float4* __restrict__ x, H8* __restrict__ o, int n8) {
    int i = blockIdx.x * blockDim.x + threadIdx.x;
    if (i >= n8) return;
    float4 v0 = x[2 * i], v1 = x[2 * i + 1];
    H8 h;
    h.a = __floats2half2_rn(v0.x, v0.y);
    h.b = __floats2half2_rn(v0.z, v0.w);
    h.c = __floats2half2_rn(v1.x, v1.y);
    h.d = __floats2half2_rn(v1.z, v1.w);
    o[i] = h;
}

__global__ void fp4lin_cvt_w(const int4* __restrict__ w, H4* __restrict__ o, int n4) {
    int i = blockIdx.x * blockDim.x + threadIdx.x;
    if (i >= n4) return;
    int4 v = w[i];
    H4 h;
    h.a = __halves2half2(__int2half_rn(v.x), __int2half_rn(v.y));
    h.b = __halves2half2(__int2half_rn(v.z), __int2half_rn(v.w));
    o[i] = h;
}

// ---------------------------------------------------------------------------
// GEMM: 256x128x64 CTA tile, 16 warps (4m x 4n, 64x32 warp tile),
// 4-stage cp.async pipeline, XOR-swizzled SMEM, HMMA m16n8k16.
//
// SMEM tile layout (A: 256 rows, B: 128 rows; 8 granules of 16B per row),
// granule stored at (g ^ (row & 7)) -> conflict-free cp.async stores AND
// conflict-free ldmatrix reads.
// ---------------------------------------------------------------------------
__global__ void __launch_bounds__(512, 1)
fp4lin_gemm(const __half* __restrict__ Ag, const __half* __restrict__ Bg,
            const float* __restrict__ scale_p, const float* __restrict__ bias,
            float* __restrict__ out) {
    extern __shared__ __align__(1024) uint8_t smem[];
    const uint32_t sbase = smem_u32(smem);
    const int tid  = threadIdx.x;
    const int wid  = tid >> 5;
    const int lane = tid & 31;
    const int wm   = wid >> 2;          // 0..3  (m warp)
    const int wn   = wid & 3;           // 0..3  (n warp)
    const int m0   = blockIdx.y * BM;
    const int n0   = blockIdx.x * BN;

    // --- cp.async per-thread mapping (fixed across stages) ---
    // A: 2048 granules -> 4 per thread (rows trow + i*64, i=0..3)
    // B: 1024 granules -> 2 per thread (rows trow + i*64, i=0..1)
    const int trow = tid >> 3;                 // 0..63
    const int tgc  = tid & 7;                  // granule col 0..7
    const uint32_t swg   = (uint32_t)(tgc ^ (trow & 7));
    const uint32_t s_off = (uint32_t)trow * 128u + swg * 16u;
    const __half* gA0 = Ag + (size_t)(m0 + trow) * K_DIM + tgc * 8;
    const __half* gB0 = Bg + (size_t)(n0 + trow) * K_DIM + tgc * 8;

    // --- ldmatrix per-lane components ---
    const int rowin  = (lane & 7) | (((lane >> 3) & 1) << 3);  // 0..15
    const int colsel = lane >> 4;                              // 0..1
    const int lane7  = lane & 7;
    uint32_t aRowOff[4];
#pragma unroll
    for (int t = 0; t < 4; t++)
        aRowOff[t] = (uint32_t)(wm * 64 + t * 16 + rowin) * 128u;
    const uint32_t bRow0 = (uint32_t)(wn * 32 + rowin) * 128u;
    const uint32_t bRow1 = (uint32_t)(wn * 32 + 16 + rowin) * 128u;

    float acc[4][4][4];
#pragma unroll
    for (int mt = 0; mt < 4; mt++)
#pragma unroll
        for (int nt = 0; nt < 4; nt++)
#pragma unroll
            for (int e = 0; e < 4; e++) acc[mt][nt][e] = 0.f;

#define LOAD_STAGE(s, kblk)                                                     \
    do {                                                                        \
        const uint32_t sA = sbase + (uint32_t)(s) * STAGE_BYTES;                \
        const uint32_t sB = sA + A_TILE_BYTES;                                  \
        _Pragma("unroll")                                                       \
        for (int i = 0; i < 4; i++)                                             \
            cp16(sA + s_off + (uint32_t)i * 64u * 128u,                         \
                 gA0 + (size_t)i * 64 * K_DIM + (kblk));                        \
        _Pragma("unroll")                                                       \
        for (int i = 0; i < 2; i++)                                             \
            cp16(sB + s_off + (uint32_t)i * 64u * 128u,                         \
                 gB0 + (size_t)i * 64 * K_DIM + (kblk));                        \
        cp_commit();                                                            \
    } while (0)

    // Prologue: fill STAGES-1 stages
#pragma unroll
    for (int s = 0; s < STAGES - 1; s++) LOAD_STAGE(s, s * BK);

    int sr = 0, sw = STAGES - 1;
    for (int k = 0; k < KITERS; k++) {
        cp_wait<STAGES - 2>();
        __syncthreads();

        // issue the next stage's loads (keeps pipeline full)
        if (k + STAGES - 1 < KITERS) LOAD_STAGE(sw, (k + STAGES - 1) * BK);
        else cp_commit();   // keep wait_group counting consistent

        const uint32_t sA = sbase + (uint32_t)sr * STAGE_BYTES;
        const uint32_t sB = sA + A_TILE_BYTES;

#pragma unroll
        for (int ks = 0; ks < BK / 16; ks++) {
            const uint32_t swz = (uint32_t)(((ks * 2 + colsel) ^ lane7)) * 16u;
            uint32_t a[4][4];
#pragma unroll
            for (int mt = 0; mt < 4; mt++)
                ldmatrix_x4(a[mt], sA + aRowOff[mt] + swz);
            uint32_t b[4][2];
            {
                uint32_t r[4];
                ldmatrix_x4(r, sB + bRow0 + swz);
                b[0][0] = r[0]; b[1][0] = r[1]; b[0][1] = r[2]; b[1][1] = r[3];
                ldmatrix_x4(r, sB + bRow1 + swz);
                b[2][0] = r[0]; b[3][0] = r[1]; b[2][1] = r[2]; b[3][1] = r[3];
            }
#pragma unroll
            for (int mt = 0; mt < 4; mt++)
#pragma unroll
                for (int nt = 0; nt < 4; nt++)
                    mma16816(acc[mt][nt], a[mt], b[nt]);
        }

        sr = (sr + 1) % STAGES;
        sw = (sw + 1) % STAGES;
    }

    // ------------------------------ epilogue -------------------------------
    const float sc = *scale_p;
    const int mbase = m0 + wm * 64 + (lane >> 2);
    const int nbase = n0 + wn * 32 + (lane & 3) * 2;
#pragma unroll
    for (int nt = 0; nt < 4; nt++) {
        const int n = nbase + nt * 8;
        const float2 bb = *reinterpret_cast<const float2*>(bias + n);
#pragma unroll
        for (int mt = 0; mt < 4; mt++) {
            const int m = mbase + mt * 16;
            float2 o0, o1;
            o0.x = acc[mt][nt][0] * sc + bb.x;
            o0.y = acc[mt][nt][1] * sc + bb.y;
            o1.x = acc[mt][nt][2] * sc + bb.x;
            o1.y = acc[mt][nt][3] * sc + bb.y;
            *reinterpret_cast<float2*>(out + (size_t)m * N_DIM + n) = o0;
            *reinterpret_cast<float2*>(out + (size_t)(m + 8) * N_DIM + n) = o1;
        }
    }
#undef LOAD_STAGE
}

// ---------------------------------------------------------------------------
// Host launch
// ---------------------------------------------------------------------------
extern "C" void kernel_launch(void* const* d_in, const int* in_sizes, int n_in,
                              void* d_out, int out_size) {
    (void)in_sizes; (void)n_in; (void)out_size;
    const float* x     = (const float*)d_in[0];
    const int*   w     = (const int*)d_in[1];
    const float* scale = (const float*)d_in[2];
    const float* bias  = (const float*)d_in[3];
    float*       out   = (float*)d_out;

    void *xh = nullptr, *wh = nullptr;
    cudaGetSymbolAddress(&xh, g_Xh);
    cudaGetSymbolAddress(&wh, g_Wh);

    {
        const int n8 = M_DIM * K_DIM / 8;
        fp4lin_cvt_x<<<n8 / 256, 256>>>((const float4*)x, (H8*)xh, n8);
        const int n4 = N_DIM * K_DIM / 4;
        fp4lin_cvt_w<<<n4 / 256, 256>>>((const int4*)w, (H4*)wh, n4);
    }

    static bool attr_set = false;
    if (!attr_set) {
        cudaFuncSetAttribute(fp4lin_gemm,
                             cudaFuncAttributeMaxDynamicSharedMemorySize,
                             SMEM_BYTES);
        attr_set = true;
    }
    dim3 grid(N_DIM / BN, M_DIM / BM);   // 32 x 32; x = n fastest
    fp4lin_gemm<<<grid, 512, SMEM_BYTES>>>((const __half*)xh, (const __half*)wh,
                                           scale, bias, out);
}